// round 1
// baseline (speedup 1.0000x reference)
#include <cuda_runtime.h>
#include <cuda_bf16.h>

#define NFIELD 39
#define EMB    16
#define VOCAB  200000
#define NFE    624      // 39*16
#define ND     64       // 32 (W1) + 32 (Wi)
#define BATCH  16384

// Pre-transposed weights: Wt[fe][d], d in [0,32) = W1[d][fe], [32,64) = Wi[d-32][fe]
__device__ float WtG[NFE * ND];

__global__ void prep_kernel(const float* __restrict__ W1, const float* __restrict__ Wi) {
    int i = blockIdx.x * blockDim.x + threadIdx.x;
    if (i >= NFE * ND) return;
    int fe = i >> 6;
    int d  = i & 63;
    WtG[i] = (d < 32) ? W1[d * NFE + fe] : Wi[(d - 32) * NFE + fe];
}

__device__ __forceinline__ unsigned long long pack2(float v) {
    unsigned long long r;
    asm("mov.b64 %0, {%1, %2};" : "=l"(r) : "f"(v), "f"(v));
    return r;
}
__device__ __forceinline__ unsigned long long fma2(unsigned long long a, unsigned long long b,
                                                   unsigned long long c) {
    unsigned long long d;
    asm("fma.rn.f32x2 %0, %1, %2, %3;" : "=l"(d) : "l"(a), "l"(b), "l"(c));
    return d;
}
__device__ __forceinline__ void unpack2(unsigned long long v, float& lo, float& hi) {
    asm("mov.b64 {%0, %1}, %2;" : "=f"(lo), "=f"(hi) : "l"(v));
}

// Shared layout (floats):
//   sW   [0, 39936)            Wt tile (full)           159744 B
//   sXv  [39936, 44928)        Xv for 128 rows           19968 B
//   sXi  [44928, 49920)        Xi for 128 rows (int)     19968 B
//   sM   [49920, 52065)        MLP weights                8580 B
#define SW_OFF  0
#define SXV_OFF 39936
#define SXI_OFF 44928
#define SM_OFF  49920
#define SMEM_FLOATS (SM_OFF + 2145)
#define SMEM_BYTES  (SMEM_FLOATS * 4)

#define ROWS_PER_BLOCK 128

__global__ __launch_bounds__(ROWS_PER_BLOCK, 1)
void pnn_kernel(const int*   __restrict__ Xi,
                const float* __restrict__ Xv,
                const float* __restrict__ tables,
                const float* __restrict__ lin1_w,
                const float* __restrict__ lin1_b,
                const float* __restrict__ lin2_w,
                const float* __restrict__ lin2_b,
                const float* __restrict__ last_w,
                const float* __restrict__ last_b,
                float*       __restrict__ out) {
    extern __shared__ float smem[];
    float* sW  = smem + SW_OFF;
    float* sXv = smem + SXV_OFF;
    int*   sXi = (int*)(smem + SXI_OFF);
    float* sM  = smem + SM_OFF;

    const int tid = threadIdx.x;
    const int b0  = blockIdx.x * ROWS_PER_BLOCK;

    // ---- stage W (full 160KB, coalesced float4 copies) ----
    {
        const float4* src = (const float4*)WtG;
        float4* dst = (float4*)sW;
        #pragma unroll 4
        for (int i = tid; i < NFE * ND / 4; i += ROWS_PER_BLOCK) dst[i] = src[i];
    }
    // ---- stage Xi/Xv for this block's 128 rows ----
    {
        const float4* srcv = (const float4*)(Xv + (size_t)b0 * NFIELD);
        float4* dstv = (float4*)sXv;
        const int4* srci = (const int4*)(Xi + (size_t)b0 * NFIELD);
        int4* dsti = (int4*)sXi;
        for (int i = tid; i < ROWS_PER_BLOCK * NFIELD / 4; i += ROWS_PER_BLOCK) {
            dstv[i] = srcv[i];
            dsti[i] = srci[i];
        }
    }
    // ---- stage MLP weights ----
    for (int i = tid; i < 1024; i += ROWS_PER_BLOCK) {
        sM[i]        = lin1_w[i];
        sM[1056 + i] = lin2_w[i];
    }
    if (tid < 32) {
        sM[1024 + tid] = lin1_b[tid];
        sM[2080 + tid] = lin2_b[tid];
        sM[2112 + tid] = last_w[tid];
    }
    if (tid == 0) sM[2144] = last_b[0];
    __syncthreads();

    // ---- per-thread row: fused GEMM [1,624]x[624,64] with f32x2 packing ----
    unsigned long long acc[32];
    #pragma unroll
    for (int k = 0; k < 32; ++k) acc[k] = 0ull;

    const int myoff = tid * NFIELD;

    // prefetch f = 0
    float xv = sXv[myoff];
    int   idx = sXi[myoff];
    const float4* rp = (const float4*)tables + ((long)0 * VOCAB + idx) * 4;
    float4 c0 = rp[0], c1 = rp[1], c2 = rp[2], c3 = rp[3];

    #pragma unroll 1
    for (int f = 0; f < NFIELD; ++f) {
        // prefetch next field's embedding row (hide DRAM latency behind compute)
        float4 n0, n1, n2, n3;
        float nxv = 0.f;
        if (f < NFIELD - 1) {
            int nidx = sXi[myoff + f + 1];
            nxv = sXv[myoff + f + 1];
            const float4* np = (const float4*)tables + ((long)(f + 1) * VOCAB + nidx) * 4;
            n0 = np[0]; n1 = np[1]; n2 = np[2]; n3 = np[3];
        } else {
            n0 = c0; n1 = c1; n2 = c2; n3 = c3;
        }

        float ev[16] = {c0.x * xv, c0.y * xv, c0.z * xv, c0.w * xv,
                        c1.x * xv, c1.y * xv, c1.z * xv, c1.w * xv,
                        c2.x * xv, c2.y * xv, c2.z * xv, c2.w * xv,
                        c3.x * xv, c3.y * xv, c3.z * xv, c3.w * xv};

        const float* wbase = sW + (size_t)f * EMB * ND;
        #pragma unroll
        for (int ee = 0; ee < EMB; ++ee) {
            unsigned long long v2 = pack2(ev[ee]);
            const ulonglong2* wrow = (const ulonglong2*)(wbase + ee * ND);
            #pragma unroll
            for (int j = 0; j < 16; ++j) {
                ulonglong2 w = wrow[j];                 // broadcast LDS.128, 1 cyc
                acc[2 * j]     = fma2(w.x, v2, acc[2 * j]);
                acc[2 * j + 1] = fma2(w.y, v2, acc[2 * j + 1]);
            }
        }

        c0 = n0; c1 = n1; c2 = n2; c3 = n3; xv = nxv;
    }

    // ---- combine: x[d] = first_order[d] + s[d]^2 ----
    float x[32];
    #pragma unroll
    for (int k = 0; k < 16; ++k) {
        float f0, f1, s0, s1;
        unpack2(acc[k],      f0, f1);
        unpack2(acc[16 + k], s0, s1);
        x[2 * k]     = fmaf(s0, s0, f0);
        x[2 * k + 1] = fmaf(s1, s1, f1);
    }

    // ---- MLP: relu(x@L1^T+b1) -> relu(@L2^T+b2) -> @last^T+lb ----
    float h1[32];
    #pragma unroll
    for (int i = 0; i < 32; ++i) {
        float t = sM[1024 + i];
        #pragma unroll
        for (int j4 = 0; j4 < 8; ++j4) {
            float4 w = *(const float4*)&sM[i * 32 + j4 * 4];
            t = fmaf(x[j4 * 4],     w.x, t);
            t = fmaf(x[j4 * 4 + 1], w.y, t);
            t = fmaf(x[j4 * 4 + 2], w.z, t);
            t = fmaf(x[j4 * 4 + 3], w.w, t);
        }
        h1[i] = fmaxf(t, 0.f);
    }
    float h2[32];
    #pragma unroll
    for (int i = 0; i < 32; ++i) {
        float t = sM[2080 + i];
        #pragma unroll
        for (int j4 = 0; j4 < 8; ++j4) {
            float4 w = *(const float4*)&sM[1056 + i * 32 + j4 * 4];
            t = fmaf(h1[j4 * 4],     w.x, t);
            t = fmaf(h1[j4 * 4 + 1], w.y, t);
            t = fmaf(h1[j4 * 4 + 2], w.z, t);
            t = fmaf(h1[j4 * 4 + 3], w.w, t);
        }
        h2[i] = fmaxf(t, 0.f);
    }
    float o = sM[2144];
    #pragma unroll
    for (int j = 0; j < 32; ++j) o = fmaf(h2[j], sM[2112 + j], o);

    out[b0 + tid] = o;
}

extern "C" void kernel_launch(void* const* d_in, const int* in_sizes, int n_in,
                              void* d_out, int out_size) {
    const int*   Xi     = (const int*)  d_in[0];
    const float* Xv     = (const float*)d_in[1];
    const float* tables = (const float*)d_in[2];
    const float* W1     = (const float*)d_in[3];
    const float* Wi     = (const float*)d_in[4];
    const float* lin1_w = (const float*)d_in[5];
    const float* lin1_b = (const float*)d_in[6];
    const float* lin2_w = (const float*)d_in[7];
    const float* lin2_b = (const float*)d_in[8];
    const float* last_w = (const float*)d_in[9];
    const float* last_b = (const float*)d_in[10];
    float* out = (float*)d_out;

    static bool attr_set = false;
    if (!attr_set) {
        cudaFuncSetAttribute(pnn_kernel, cudaFuncAttributeMaxDynamicSharedMemorySize, SMEM_BYTES);
        attr_set = true;
    }

    prep_kernel<<<(NFE * ND + 255) / 256, 256>>>(W1, Wi);
    pnn_kernel<<<BATCH / ROWS_PER_BLOCK, ROWS_PER_BLOCK, SMEM_BYTES>>>(
        Xi, Xv, tables, lin1_w, lin1_b, lin2_w, lin2_b, last_w, last_b, out);
}